// round 2
// baseline (speedup 1.0000x reference)
#include <cuda_runtime.h>
#include <cstdint>

typedef unsigned long long ull;

#define NB_MAX 32768
#define NCH 18

// Scratch: 18 channel bitmasks per board (4.7 MB). __device__ global = allowed.
__device__ ull g_masks[(size_t)NB_MAX * NCH];

// ---------- bit helpers (bit index = i*8 + j, row-major) ----------
#define FILE_A 0x0101010101010101ULL   // column 0
#define FILE_H 0x8080808080808080ULL   // column 7
#define ALL64  0xFFFFFFFFFFFFFFFFULL
#define COLS_GE3 0xF8F8F8F8F8F8F8F8ULL // columns 3..7

// R(n): bit at col k <- source col k+n (look right within row)
__device__ __forceinline__ ull Rs(ull x, int n) {
    const ull m = (0xFFULL >> n) * FILE_A;   // byte = 0xFF>>n replicated
    return (x >> n) & m;
}
// L(n): bit at col k <- source col k-n (look left within row)
__device__ __forceinline__ ull Ls(ull x, int n) {
    const ull m = ((0xFFULL << n) & 0xFFULL) * FILE_A;
    return (x << n) & m;
}

// 8x8 bit transpose (flip about main diagonal), Hacker's Delight
__device__ __forceinline__ ull tr8(ull x) {
    ull t;
    t = (x ^ (x >> 7))  & 0x00AA00AA00AA00AAULL; x = x ^ t ^ (t << 7);
    t = (x ^ (x >> 14)) & 0x0000CCCC0000CCCCULL; x = x ^ t ^ (t << 14);
    t = (x ^ (x >> 28)) & 0x00000000F0F0F0F0ULL; x = x ^ t ^ (t << 28);
    return x;
}

// Exact-run-length classification along one direction.
// F(x) = (x<<sh)&fm moves mask forward along dir; B(x) = (x>>sh)&bm backward.
// L_a = ">= a consecutive set cells ending here (backwards incl self)",
// R_b likewise forward.  run >= N  <=>  OR_{a+b=N+1} (L_a & R_b).
__device__ __forceinline__ void run_eq(ull m, int sh, ull fm, ull bm,
                                       ull& e1, ull& e2, ull& e3) {
    ull L1 = m;
    ull L2 = m & ((L1 << sh) & fm);
    ull L3 = m & ((L2 << sh) & fm);
    ull L4 = m & ((L3 << sh) & fm);
    ull R1 = m;
    ull R2 = m & ((R1 >> sh) & bm);
    ull R3 = m & ((R2 >> sh) & bm);
    ull R4 = m & ((R3 >> sh) & bm);
    ull ge2 = (L1 & R2) | (L2 & R1);
    ull ge3 = (L1 & R3) | (L2 & R2) | (L3 & R1);
    ull ge4 = (L1 & R4) | (L2 & R3) | (L3 & R2) | (L4 & R1);
    e1 |= m   & ~ge2;
    e2 |= ge2 & ~ge3;
    e3 |= ge3 & ~ge4;
}

// conn_channels(m, [1,2,3]) : OR over the 4 directions of (run == N)
__device__ __forceinline__ void conn3(ull m, ull& c1, ull& c2, ull& c3) {
    c1 = 0; c2 = 0; c3 = 0;
    run_eq(m, 1, ~FILE_A, ~FILE_H, c1, c2, c3);  // (0,1)  horizontal
    run_eq(m, 8, ALL64,   ALL64,   c1, c2, c3);  // (1,0)  vertical
    run_eq(m, 9, ~FILE_A, ~FILE_H, c1, c2, c3);  // (1,1)  diagonal
    run_eq(m, 7, ~FILE_H, ~FILE_A, c1, c2, c3);  // (1,-1) anti-diagonal
}

// Row-direction line features (along j). Bound checks are implicit: the
// Rs(.,n) masks zero any window starting beyond column 7-n.
// blocked(idx) reduces to:  op[idx]  (in range)  |  edge.
__device__ __forceinline__ void line_feats(ull me, ull op, ull empty,
                                           ull& live2, ull& live3, ull& rush3) {
    ull me1 = Rs(me, 1), me2 = Rs(me, 2), me3 = Rs(me, 3);
    ull notme = ~me;

    // live2
    ull A  = me    & me1 & Rs(empty, 2) & Rs(empty, 3);           // k..k+1 marked
    ull Bm = empty & me1 & me2          & Rs(empty, 3);           // k+1..k+2 marked
    live2 = A | Ls(A, 1) | Ls(Bm, 1) | Ls(Bm, 2);

    // live3
    ull core = me1 & me2 & me3;                                   // me[k+1..k+3]
    ull Cm = empty & core & Rs(empty, 4);                         // k+1..k+3 marked
    live3 = Ls(Cm, 1) | Ls(Cm, 2) | Ls(Cm, 3);

    // rush3
    ull lb = Ls(op, 1) | FILE_A;          // blocked(k-1)
    ull rb = Rs(op, 5) | COLS_GE3;        // blocked(k+5)  (k=3 -> edge)
    ull Dm = me & me1 & me2 & Rs(empty, 3) & Rs(notme, 4) & lb;   // k..k+2 marked
    ull open3 = notme & core & Rs(notme, 4);
    ull Em = open3 & (lb ^ rb);                                    // k+1..k+3 marked
    rush3 = Dm | Ls(Dm, 1) | Ls(Dm, 2) | Ls(Em, 1) | Ls(Em, 2) | Ls(Em, 3);
}

// rows + transposed columns, OR'd
__device__ __forceinline__ void live_rush(ull me, ull op,
                                          ull& l2, ull& l3, ull& r3) {
    ull empty = ~(me | op);
    ull a, b, c;   line_feats(me, op, empty, a, b, c);
    ull a2, b2, c2;
    line_feats(tr8(me), tr8(op), tr8(empty), a2, b2, c2);
    l2 = a | tr8(a2);
    l3 = b | tr8(b2);
    r3 = c | tr8(c2);
}

// ---------------- kernel 1: per-board feature masks ----------------
__global__ void feat_kernel(const float* __restrict__ state,
                            const float* __restrict__ side, int nb) {
    int b = blockIdx.x * blockDim.x + threadIdx.x;
    if (b >= nb) return;

    float s  = side[b];
    float ns = -s;
    const float4* sp = reinterpret_cast<const float4*>(state) + (size_t)b * 16;

    ull my = 0, op = 0;
#pragma unroll
    for (int q = 0; q < 16; q++) {
        float4 v = sp[q];
        int base = q * 4;
        my |= ((ull)(v.x == s)  << base)       | ((ull)(v.y == s)  << (base + 1))
            | ((ull)(v.z == s)  << (base + 2)) | ((ull)(v.w == s)  << (base + 3));
        op |= ((ull)(v.x == ns) << base)       | ((ull)(v.y == ns) << (base + 1))
            | ((ull)(v.z == ns) << (base + 2)) | ((ull)(v.w == ns) << (base + 3));
    }

    ull ch[NCH];
    ch[0] = my;
    ch[1] = op;
    conn3(my, ch[2], ch[3], ch[4]);
    conn3(op, ch[5], ch[6], ch[7]);

    ull l2m, l3m, r3m, l2o, l3o, r3o;
    live_rush(my, op, l2m, l3m, r3m);
    live_rush(op, my, l2o, l3o, r3o);
    ch[8]  = l2m; ch[9]  = l3m; ch[10] = r3m;
    ch[11] = (__popcll(l2m) >= 2) ? ALL64 : 0ULL;
    ch[12] = ((__popcll(l3m) + __popcll(r3m)) >= 2) ? ALL64 : 0ULL;
    ch[13] = l2o; ch[14] = l3o; ch[15] = r3o;
    ch[16] = (__popcll(l2o) >= 2) ? ALL64 : 0ULL;
    ch[17] = ((__popcll(l3o) + __popcll(r3o)) >= 2) ? ALL64 : 0ULL;

    ull* dst = g_masks + (size_t)b * NCH;
#pragma unroll
    for (int c = 0; c < NCH; c++) dst[c] = ch[c];
}

// ---------------- kernel 2: coalesced bit -> float expansion ----------------
// One thread per float4 (= 4 cells). 288 float4 per board (18 ch * 16 nibbles).
__global__ void expand_kernel(float4* __restrict__ out, int n4) {
    int i = blockIdx.x * blockDim.x + threadIdx.x;
    if (i >= n4) return;
    int board = i / 288;
    int rem   = i - board * 288;
    int chn   = rem >> 4;        // channel 0..17
    int nib   = rem & 15;        // nibble within 64-bit mask
    ull m = __ldg(&g_masks[(size_t)board * NCH + chn]);
    unsigned bits = (unsigned)(m >> (nib * 4)) & 0xFu;
    float4 o;
    o.x = (bits & 1u) ? 1.0f : 0.0f;
    o.y = (bits & 2u) ? 1.0f : 0.0f;
    o.z = (bits & 4u) ? 1.0f : 0.0f;
    o.w = (bits & 8u) ? 1.0f : 0.0f;
    out[i] = o;
}

extern "C" void kernel_launch(void* const* d_in, const int* in_sizes, int n_in,
                              void* d_out, int out_size) {
    const float* state = (const float*)d_in[0];
    const float* side  = (const float*)d_in[1];
    int nb = in_sizes[0] / 64;                 // boards
    if (nb > NB_MAX) nb = NB_MAX;

    int blocks1 = (nb + 127) / 128;
    feat_kernel<<<blocks1, 128>>>(state, side, nb);

    int n4 = out_size / 4;                     // float4 count
    int blocks2 = (n4 + 255) / 256;
    expand_kernel<<<blocks2, 256>>>((float4*)d_out, n4);
}

// round 3
// speedup vs baseline: 1.1367x; 1.1367x over previous
#include <cuda_runtime.h>
#include <cstdint>

typedef unsigned long long ull;

#define NCH 18
#define TPB 64          // threads per block == boards per block

// ---------- bit helpers (bit index = i*8 + j, row-major) ----------
#define FILE_A 0x0101010101010101ULL   // column 0
#define FILE_H 0x8080808080808080ULL   // column 7
#define ALL64  0xFFFFFFFFFFFFFFFFULL
#define COLS_GE3 0xF8F8F8F8F8F8F8F8ULL // columns 3..7

// R(n): bit at col k <- source col k+n (look right within row)
__device__ __forceinline__ ull Rs(ull x, int n) {
    const ull m = (0xFFULL >> n) * FILE_A;
    return (x >> n) & m;
}
// L(n): bit at col k <- source col k-n (look left within row)
__device__ __forceinline__ ull Ls(ull x, int n) {
    const ull m = ((0xFFULL << n) & 0xFFULL) * FILE_A;
    return (x << n) & m;
}

// 8x8 bit transpose (flip about main diagonal)
__device__ __forceinline__ ull tr8(ull x) {
    ull t;
    t = (x ^ (x >> 7))  & 0x00AA00AA00AA00AAULL; x = x ^ t ^ (t << 7);
    t = (x ^ (x >> 14)) & 0x0000CCCC0000CCCCULL; x = x ^ t ^ (t << 14);
    t = (x ^ (x >> 28)) & 0x00000000F0F0F0F0ULL; x = x ^ t ^ (t << 28);
    return x;
}

// Exact-run-length classification along one direction.
__device__ __forceinline__ void run_eq(ull m, int sh, ull fm, ull bm,
                                       ull& e1, ull& e2, ull& e3) {
    ull L1 = m;
    ull L2 = m & ((L1 << sh) & fm);
    ull L3 = m & ((L2 << sh) & fm);
    ull L4 = m & ((L3 << sh) & fm);
    ull R1 = m;
    ull R2 = m & ((R1 >> sh) & bm);
    ull R3 = m & ((R2 >> sh) & bm);
    ull R4 = m & ((R3 >> sh) & bm);
    ull ge2 = (L1 & R2) | (L2 & R1);
    ull ge3 = (L1 & R3) | (L2 & R2) | (L3 & R1);
    ull ge4 = (L1 & R4) | (L2 & R3) | (L3 & R2) | (L4 & R1);
    e1 |= m   & ~ge2;
    e2 |= ge2 & ~ge3;
    e3 |= ge3 & ~ge4;
}

__device__ __forceinline__ void conn3(ull m, ull& c1, ull& c2, ull& c3) {
    c1 = 0; c2 = 0; c3 = 0;
    run_eq(m, 1, ~FILE_A, ~FILE_H, c1, c2, c3);  // (0,1)
    run_eq(m, 8, ALL64,   ALL64,   c1, c2, c3);  // (1,0)
    run_eq(m, 9, ~FILE_A, ~FILE_H, c1, c2, c3);  // (1,1)
    run_eq(m, 7, ~FILE_H, ~FILE_A, c1, c2, c3);  // (1,-1)
}

__device__ __forceinline__ void line_feats(ull me, ull op, ull empty,
                                           ull& live2, ull& live3, ull& rush3) {
    ull me1 = Rs(me, 1), me2 = Rs(me, 2), me3 = Rs(me, 3);
    ull notme = ~me;

    // live2
    ull A  = me    & me1 & Rs(empty, 2) & Rs(empty, 3);
    ull Bm = empty & me1 & me2          & Rs(empty, 3);
    live2 = A | Ls(A, 1) | Ls(Bm, 1) | Ls(Bm, 2);

    // live3
    ull core = me1 & me2 & me3;
    ull Cm = empty & core & Rs(empty, 4);
    live3 = Ls(Cm, 1) | Ls(Cm, 2) | Ls(Cm, 3);

    // rush3
    ull lb = Ls(op, 1) | FILE_A;
    ull rb = Rs(op, 5) | COLS_GE3;
    ull Dm = me & me1 & me2 & Rs(empty, 3) & Rs(notme, 4) & lb;
    ull open3 = notme & core & Rs(notme, 4);
    ull Em = open3 & (lb ^ rb);
    rush3 = Dm | Ls(Dm, 1) | Ls(Dm, 2) | Ls(Em, 1) | Ls(Em, 2) | Ls(Em, 3);
}

__device__ __forceinline__ void live_rush(ull me, ull op,
                                          ull& l2, ull& l3, ull& r3) {
    ull empty = ~(me | op);
    ull a, b, c;   line_feats(me, op, empty, a, b, c);
    ull a2, b2, c2;
    line_feats(tr8(me), tr8(op), tr8(empty), a2, b2, c2);
    l2 = a | tr8(a2);
    l3 = b | tr8(b2);
    r3 = c | tr8(c2);
}

// ---------------- fused kernel ----------------
// Phase 1: each thread computes one board's 18 channel masks -> smem.
// Phase 2: whole block expands its 64 boards' bits into coalesced float4 stores.
__global__ void __launch_bounds__(TPB)
fused_kernel(const float* __restrict__ state,
             const float* __restrict__ side,
             float4* __restrict__ out, int nb) {
    __shared__ ull masks[TPB * NCH];

    int t  = threadIdx.x;
    int b0 = blockIdx.x * TPB;
    int b  = b0 + t;

    if (b < nb) {
        float s  = side[b];
        float ns = -s;
        const float4* sp = reinterpret_cast<const float4*>(state) + (size_t)b * 16;

        ull my = 0, op = 0;
#pragma unroll
        for (int q = 0; q < 16; q++) {
            float4 v = sp[q];
            int base = q * 4;
            my |= ((ull)(v.x == s)  << base)       | ((ull)(v.y == s)  << (base + 1))
                | ((ull)(v.z == s)  << (base + 2)) | ((ull)(v.w == s)  << (base + 3));
            op |= ((ull)(v.x == ns) << base)       | ((ull)(v.y == ns) << (base + 1))
                | ((ull)(v.z == ns) << (base + 2)) | ((ull)(v.w == ns) << (base + 3));
        }

        ull ch[NCH];
        ch[0] = my;
        ch[1] = op;
        conn3(my, ch[2], ch[3], ch[4]);
        conn3(op, ch[5], ch[6], ch[7]);

        ull l2m, l3m, r3m, l2o, l3o, r3o;
        live_rush(my, op, l2m, l3m, r3m);
        live_rush(op, my, l2o, l3o, r3o);
        ch[8]  = l2m; ch[9]  = l3m; ch[10] = r3m;
        ch[11] = (__popcll(l2m) >= 2) ? ALL64 : 0ULL;
        ch[12] = ((__popcll(l3m) + __popcll(r3m)) >= 2) ? ALL64 : 0ULL;
        ch[13] = l2o; ch[14] = l3o; ch[15] = r3o;
        ch[16] = (__popcll(l2o) >= 2) ? ALL64 : 0ULL;
        ch[17] = ((__popcll(l3o) + __popcll(r3o)) >= 2) ? ALL64 : 0ULL;

#pragma unroll
        for (int c = 0; c < NCH; c++) masks[t * NCH + c] = ch[c];
    }
    __syncthreads();

    // Phase 2: expand. Block output chunk = nBoards * 288 float4, contiguous.
    int nBoards = nb - b0;
    if (nBoards > TPB) nBoards = TPB;
    if (nBoards <= 0) return;
    int nf4 = nBoards * 288;                  // 18 ch * 16 nibbles per board
    float4* dst = out + (size_t)b0 * 288;

    const unsigned* mw = reinterpret_cast<const unsigned*>(masks);
    const unsigned one = 0x3F800000u;         // 1.0f bits

    int rem = t;          // position within current board's 288 float4
    int board = 0;
#pragma unroll 4
    for (int i = t; i < nf4; i += TPB) {
        int chn = rem >> 4;                   // channel 0..17
        int nib = rem & 15;                   // nibble within 64-bit mask
        unsigned w = mw[(board * NCH + chn) * 2 + (nib >> 3)];
        unsigned bits = (w >> ((nib & 7) * 4)) & 0xFu;
        float4 o;
        o.x = __uint_as_float((bits & 1u) ? one : 0u);
        o.y = __uint_as_float((bits & 2u) ? one : 0u);
        o.z = __uint_as_float((bits & 4u) ? one : 0u);
        o.w = __uint_as_float((bits & 8u) ? one : 0u);
        dst[i] = o;
        rem += TPB;
        if (rem >= 288) { rem -= 288; board++; }
    }
}

extern "C" void kernel_launch(void* const* d_in, const int* in_sizes, int n_in,
                              void* d_out, int out_size) {
    const float* state = (const float*)d_in[0];
    const float* side  = (const float*)d_in[1];
    int nb = in_sizes[0] / 64;                 // boards

    int blocks = (nb + TPB - 1) / TPB;
    fused_kernel<<<blocks, TPB>>>(state, side, (float4*)d_out, nb);
}

// round 4
// speedup vs baseline: 1.2053x; 1.0603x over previous
#include <cuda_runtime.h>
#include <cstdint>

typedef unsigned long long ull;

#define NCH 18
#define BPB 64          // boards per block
#define TPB 512         // threads per block (expansion parallelism)

// ---------- bit helpers (bit index = i*8 + j, row-major) ----------
#define FILE_A 0x0101010101010101ULL   // column 0
#define FILE_H 0x8080808080808080ULL   // column 7
#define ALL64  0xFFFFFFFFFFFFFFFFULL
#define COLS_GE3 0xF8F8F8F8F8F8F8F8ULL // columns 3..7

__device__ __forceinline__ ull Rs(ull x, int n) {
    const ull m = (0xFFULL >> n) * FILE_A;
    return (x >> n) & m;
}
__device__ __forceinline__ ull Ls(ull x, int n) {
    const ull m = ((0xFFULL << n) & 0xFFULL) * FILE_A;
    return (x << n) & m;
}

// 8x8 bit transpose (flip about main diagonal)
__device__ __forceinline__ ull tr8(ull x) {
    ull t;
    t = (x ^ (x >> 7))  & 0x00AA00AA00AA00AAULL; x = x ^ t ^ (t << 7);
    t = (x ^ (x >> 14)) & 0x0000CCCC0000CCCCULL; x = x ^ t ^ (t << 14);
    t = (x ^ (x >> 28)) & 0x00000000F0F0F0F0ULL; x = x ^ t ^ (t << 28);
    return x;
}

// Exact-run-length classification along one direction.
__device__ __forceinline__ void run_eq(ull m, int sh, ull fm, ull bm,
                                       ull& e1, ull& e2, ull& e3) {
    ull L1 = m;
    ull L2 = m & ((L1 << sh) & fm);
    ull L3 = m & ((L2 << sh) & fm);
    ull L4 = m & ((L3 << sh) & fm);
    ull R1 = m;
    ull R2 = m & ((R1 >> sh) & bm);
    ull R3 = m & ((R2 >> sh) & bm);
    ull R4 = m & ((R3 >> sh) & bm);
    ull ge2 = (L1 & R2) | (L2 & R1);
    ull ge3 = (L1 & R3) | (L2 & R2) | (L3 & R1);
    ull ge4 = (L1 & R4) | (L2 & R3) | (L3 & R2) | (L4 & R1);
    e1 |= m   & ~ge2;
    e2 |= ge2 & ~ge3;
    e3 |= ge3 & ~ge4;
}

__device__ __forceinline__ void conn3(ull m, ull& c1, ull& c2, ull& c3) {
    c1 = 0; c2 = 0; c3 = 0;
    run_eq(m, 1, ~FILE_A, ~FILE_H, c1, c2, c3);  // (0,1)
    run_eq(m, 8, ALL64,   ALL64,   c1, c2, c3);  // (1,0)
    run_eq(m, 9, ~FILE_A, ~FILE_H, c1, c2, c3);  // (1,1)
    run_eq(m, 7, ~FILE_H, ~FILE_A, c1, c2, c3);  // (1,-1)
}

__device__ __forceinline__ void line_feats(ull me, ull op, ull empty,
                                           ull& live2, ull& live3, ull& rush3) {
    ull me1 = Rs(me, 1), me2 = Rs(me, 2), me3 = Rs(me, 3);
    ull notme = ~me;

    // live2
    ull A  = me    & me1 & Rs(empty, 2) & Rs(empty, 3);
    ull Bm = empty & me1 & me2          & Rs(empty, 3);
    live2 = A | Ls(A, 1) | Ls(Bm, 1) | Ls(Bm, 2);

    // live3
    ull core = me1 & me2 & me3;
    ull Cm = empty & core & Rs(empty, 4);
    live3 = Ls(Cm, 1) | Ls(Cm, 2) | Ls(Cm, 3);

    // rush3
    ull lb = Ls(op, 1) | FILE_A;
    ull rb = Rs(op, 5) | COLS_GE3;
    ull Dm = me & me1 & me2 & Rs(empty, 3) & Rs(notme, 4) & lb;
    ull open3 = notme & core & Rs(notme, 4);
    ull Em = open3 & (lb ^ rb);
    rush3 = Dm | Ls(Dm, 1) | Ls(Dm, 2) | Ls(Em, 1) | Ls(Em, 2) | Ls(Em, 3);
}

__device__ __forceinline__ void live_rush(ull me, ull op,
                                          ull& l2, ull& l3, ull& r3) {
    ull empty = ~(me | op);
    ull a, b, c;   line_feats(me, op, empty, a, b, c);
    ull a2, b2, c2;
    line_feats(tr8(me), tr8(op), tr8(empty), a2, b2, c2);
    l2 = a | tr8(a2);
    l3 = b | tr8(b2);
    r3 = c | tr8(c2);
}

// ---------------- fused kernel ----------------
// Phase 1: threads 0..BPB-1 each compute one board's 18 channel masks -> smem.
// Phase 2: all TPB threads expand the block's BPB*288 float4 coalesced stores.
__global__ void __launch_bounds__(TPB)
fused_kernel(const float* __restrict__ state,
             const float* __restrict__ side,
             float4* __restrict__ out, int nb) {
    __shared__ ull masks[BPB * NCH];

    int t  = threadIdx.x;
    int b0 = blockIdx.x * BPB;
    int b  = b0 + t;

    if (t < BPB && b < nb) {
        float s  = side[b];
        float ns = -s;
        const float4* sp = reinterpret_cast<const float4*>(state) + (size_t)b * 16;

        ull my = 0, op = 0;
#pragma unroll
        for (int q = 0; q < 16; q++) {
            float4 v = sp[q];
            int base = q * 4;
            my |= ((ull)(v.x == s)  << base)       | ((ull)(v.y == s)  << (base + 1))
                | ((ull)(v.z == s)  << (base + 2)) | ((ull)(v.w == s)  << (base + 3));
            op |= ((ull)(v.x == ns) << base)       | ((ull)(v.y == ns) << (base + 1))
                | ((ull)(v.z == ns) << (base + 2)) | ((ull)(v.w == ns) << (base + 3));
        }

        ull ch[NCH];
        ch[0] = my;
        ch[1] = op;
        conn3(my, ch[2], ch[3], ch[4]);
        conn3(op, ch[5], ch[6], ch[7]);

        ull l2m, l3m, r3m, l2o, l3o, r3o;
        live_rush(my, op, l2m, l3m, r3m);
        live_rush(op, my, l2o, l3o, r3o);
        ch[8]  = l2m; ch[9]  = l3m; ch[10] = r3m;
        ch[11] = (__popcll(l2m) >= 2) ? ALL64 : 0ULL;
        ch[12] = ((__popcll(l3m) + __popcll(r3m)) >= 2) ? ALL64 : 0ULL;
        ch[13] = l2o; ch[14] = l3o; ch[15] = r3o;
        ch[16] = (__popcll(l2o) >= 2) ? ALL64 : 0ULL;
        ch[17] = ((__popcll(l3o) + __popcll(r3o)) >= 2) ? ALL64 : 0ULL;

#pragma unroll
        for (int c = 0; c < NCH; c++) masks[t * NCH + c] = ch[c];
    }
    __syncthreads();

    // Phase 2: expand. Block output chunk = nBoards * 288 float4, contiguous.
    int nBoards = nb - b0;
    if (nBoards > BPB) nBoards = BPB;
    if (nBoards <= 0) return;
    int nf4 = nBoards * 288;                  // 18 ch * 16 nibbles per board
    float4* dst = out + (size_t)b0 * 288;

    const unsigned* mw = reinterpret_cast<const unsigned*>(masks);
    const unsigned one = 0x3F800000u;         // 1.0f bits

#pragma unroll 4
    for (int i = t; i < nf4; i += TPB) {
        int board = i / 288;                  // mul-shift, constant divisor
        int rem   = i - board * 288;
        int chn = rem >> 4;                   // channel 0..17
        int nib = rem & 15;                   // nibble within 64-bit mask
        unsigned w = mw[(board * NCH + chn) * 2 + (nib >> 3)];
        unsigned bits = (w >> ((nib & 7) * 4)) & 0xFu;
        float4 o;
        o.x = __uint_as_float((bits & 1u) ? one : 0u);
        o.y = __uint_as_float((bits & 2u) ? one : 0u);
        o.z = __uint_as_float((bits & 4u) ? one : 0u);
        o.w = __uint_as_float((bits & 8u) ? one : 0u);
        dst[i] = o;
    }
}

extern "C" void kernel_launch(void* const* d_in, const int* in_sizes, int n_in,
                              void* d_out, int out_size) {
    const float* state = (const float*)d_in[0];
    const float* side  = (const float*)d_in[1];
    int nb = in_sizes[0] / 64;                 // boards

    int blocks = (nb + BPB - 1) / BPB;
    fused_kernel<<<blocks, TPB>>>(state, side, (float4*)d_out, nb);
}